// round 12
// baseline (speedup 1.0000x reference)
#include <cuda_runtime.h>

typedef unsigned long long ull;

// conv1 weights: plain (cos,sin) per tap, [o][k] k=di*2+dj -> float4 = 2 taps
__device__ __align__(16) float2 g_w1c[16];
// conv2 weights, tap-paired: ulonglong2 per (c,di,djpair,o): .x=(c0,c1) .y=(s0,s1)
//   index = ((c*4+di)*2 + h)*8 + o   (h = dj>>1)
__device__ __align__(16) float g_w2p[2048];
__device__ __align__(16) float2 g_ffwc[2880];  // [n][j] (cos,sin)

__global__ void precompute_weights(const float* __restrict__ w1,
                                   const float* __restrict__ w2,
                                   const float* __restrict__ ffw) {
    int i = blockIdx.x * blockDim.x + threadIdx.x;
    if (i < 16) {
        float s, c; sincosf(w1[i], &s, &c);
        g_w1c[i] = make_float2(c, s);
    } else if (i < 528) {
        int t = i - 16;
        int o = t >> 6, r = t & 63;                  // [o][c][di][dj]
        int cc = r >> 4, di = (r >> 2) & 3, dj = r & 3;
        float s, c; sincosf(w2[t], &s, &c);
        int base = ((((cc * 4 + di) * 2 + (dj >> 1)) * 8 + o)) * 4;
        g_w2p[base + (dj & 1)]     = c;
        g_w2p[base + 2 + (dj & 1)] = s;
    } else if (i < 3408) {
        int t = i - 528;
        int j = t / 10, n = t % 10;                  // [j][n] -> [n][j]
        float s, c; sincosf(ffw[t], &s, &c);
        g_ffwc[n * 288 + j] = make_float2(c, s);
    }
}

// ---- packed f32x2 helpers ----
__device__ __forceinline__ ull pack2(float lo, float hi) {
    ull r; asm("mov.b64 %0, {%1,%2};" : "=l"(r) : "f"(lo), "f"(hi)); return r;
}
__device__ __forceinline__ void unpack2(ull a, float& lo, float& hi) {
    asm("mov.b64 {%0,%1}, %2;" : "=f"(lo), "=f"(hi) : "l"(a));
}
__device__ __forceinline__ ull fma2(ull a, ull b, ull c) {
    ull d; asm("fma.rn.f32x2 %0, %1, %2, %3;" : "=l"(d) : "l"(a), "l"(b), "l"(c));
    return d;
}
#define SGN2 0x8000000080000000ULL
// finalize: Sx = X.lo+X.hi ; Sy = Y.lo+Y.hi ; normalize to unit phasor
__device__ __forceinline__ float2 final_dir(ull X, ull Y) {
    float xl, xh, yl, yh;
    unpack2(X, xl, xh); unpack2(Y, yl, yh);
    float Sx = xl + xh, Sy = yl + yh;
    float inv = rsqrtf(fmaxf(Sx * Sx + Sy * Sy, 1e-36f));
    return make_float2(Sx * inv, Sy * inv);
}

__global__ __launch_bounds__(160, 7)
void ringnn_kernel(const float* __restrict__ x, float* __restrict__ out) {
    // conv1 out, tap-paired: per (img,c,row i,pair k): { (x0,x1), (y0,y1) }
    __shared__ __align__(16) ulonglong2 s_e1u[2 * 392];   // img*392 + (c*14+i)*7+k
    __shared__ __align__(16) float2 s_f[2][288];          // conv2 out, plain
    __shared__ __align__(16) float4 s_w2[256];            // tap-paired conv2 w

    const int tid = threadIdx.x;
    const int b = blockIdx.x;            // images 2b, 2b+1

    for (int i = tid; i < 256; i += 160)
        s_w2[i] = ((const float4*)g_w2p)[i];  // phase 3 reads after the sync below

    // ---- Phase 1+2 fused: thread = pair of adjacent conv1 patches ----
    const float* xb = x + (size_t)b * 1568;
    for (int t = tid; t < 196; t += 160) {
        int img = t / 98, pp = t % 98;
        int i = pp / 7, k = pp % 7;                 // row i, pair k (cols 4k..4k+3)
        const float* px = xb + img * 784 + (2 * i) * 28 + 4 * k;
        float4 r0 = __ldg((const float4*)px);        // top row, both patches
        float4 r1 = __ldg((const float4*)(px + 28)); // bottom row
        float pc[8], ps[8];                          // patch0: 0..3 ; patch1: 4..7
        __sincosf(r0.x, &ps[0], &pc[0]);
        __sincosf(r0.y, &ps[1], &pc[1]);
        __sincosf(r1.x, &ps[2], &pc[2]);
        __sincosf(r1.y, &ps[3], &pc[3]);
        __sincosf(r0.z, &ps[4], &pc[4]);
        __sincosf(r0.w, &ps[5], &pc[5]);
        __sincosf(r1.z, &ps[6], &pc[6]);
        __sincosf(r1.w, &ps[7], &pc[7]);
        #pragma unroll
        for (int c = 0; c < 4; c++) {
            float4 wa = __ldg((const float4*)g_w1c + c * 2);     // taps 0,1 (c,s,c,s)
            float4 wb = __ldg((const float4*)g_w1c + c * 2 + 1); // taps 2,3
            float S0x, S0y, S1x, S1y;
            S0x = pc[0]*wa.x + ps[0]*wa.y + pc[1]*wa.z + ps[1]*wa.w
                + pc[2]*wb.x + ps[2]*wb.y + pc[3]*wb.z + ps[3]*wb.w;
            S0y = ps[0]*wa.x - pc[0]*wa.y + ps[1]*wa.z - pc[1]*wa.w
                + ps[2]*wb.x - pc[2]*wb.y + ps[3]*wb.z - pc[3]*wb.w;
            S1x = pc[4]*wa.x + ps[4]*wa.y + pc[5]*wa.z + ps[5]*wa.w
                + pc[6]*wb.x + ps[6]*wb.y + pc[7]*wb.z + ps[7]*wb.w;
            S1y = ps[4]*wa.x - pc[4]*wa.y + ps[5]*wa.z - pc[5]*wa.w
                + ps[6]*wb.x - pc[6]*wb.y + ps[7]*wb.z - pc[7]*wb.w;
            float i0 = rsqrtf(fmaxf(S0x*S0x + S0y*S0y, 1e-36f));
            float i1 = rsqrtf(fmaxf(S1x*S1x + S1y*S1y, 1e-36f));
            ulonglong2 e;
            e.x = pack2(S0x * i0, S1x * i1);   // (x0, x1)
            e.y = pack2(S0y * i0, S1y * i1);   // (y0, y1)
            s_e1u[img * 392 + (c * 14 + i) * 7 + k] = e;
        }
    }
    __syncthreads();

    // ---- Phase 3: conv2, 2x2 output tile; per-c row loop loads each of the
    //      6 needed input rows exactly once (rows 4up+2,4up+3 feed BOTH u-outputs)
    if (tid < 144) {
        int img = tid / 144 + (tid >> 3) / 9;        // 0 for tid<72, 1 for 72..143
        int rr = tid % 72;
        int o = rr & 7, t9 = rr >> 3;
        int up = t9 / 3, vp = t9 % 3;
        img = tid / 72;                               // (clean recompute)
        const ulonglong2* e1u = s_e1u + img * 392;
        const ulonglong2* w2u = (const ulonglong2*)s_w2;
        ull X00=0, Y00=0, X01=0, Y01=0, X10=0, Y10=0, X11=0, Y11=0;
        #pragma unroll
        for (int c = 0; c < 4; c++) {
            ulonglong2 W[4][2];                       // all 8 weight pairs for this c
            #pragma unroll
            for (int di = 0; di < 4; di++) {
                int wb = ((c * 4 + di) * 2) * 8 + o;
                W[di][0] = w2u[wb];
                W[di][1] = w2u[wb + 8];
            }
            int rb = (c * 14 + 4 * up) * 7 + 2 * vp;
            #pragma unroll
            for (int r6 = 0; r6 < 6; r6++) {
                ulonglong2 A0 = e1u[rb + r6 * 7];
                ulonglong2 A1 = e1u[rb + r6 * 7 + 1];
                ulonglong2 A2 = e1u[rb + r6 * 7 + 2];
                if (r6 < 4) {                         // u0 = 2up, di = r6
                    ull n0 = W[r6][0].y ^ SGN2;
                    ull n1 = W[r6][1].y ^ SGN2;
                    X00 = fma2(A0.x, W[r6][0].x, X00); X00 = fma2(A0.y, W[r6][0].y, X00);
                    X00 = fma2(A1.x, W[r6][1].x, X00); X00 = fma2(A1.y, W[r6][1].y, X00);
                    Y00 = fma2(A0.y, W[r6][0].x, Y00); Y00 = fma2(A0.x, n0, Y00);
                    Y00 = fma2(A1.y, W[r6][1].x, Y00); Y00 = fma2(A1.x, n1, Y00);
                    X01 = fma2(A1.x, W[r6][0].x, X01); X01 = fma2(A1.y, W[r6][0].y, X01);
                    X01 = fma2(A2.x, W[r6][1].x, X01); X01 = fma2(A2.y, W[r6][1].y, X01);
                    Y01 = fma2(A1.y, W[r6][0].x, Y01); Y01 = fma2(A1.x, n0, Y01);
                    Y01 = fma2(A2.y, W[r6][1].x, Y01); Y01 = fma2(A2.x, n1, Y01);
                }
                if (r6 >= 2) {                        // u1 = 2up+1, di = r6-2
                    const int d2 = r6 - 2;
                    ull m0 = W[d2][0].y ^ SGN2;
                    ull m1 = W[d2][1].y ^ SGN2;
                    X10 = fma2(A0.x, W[d2][0].x, X10); X10 = fma2(A0.y, W[d2][0].y, X10);
                    X10 = fma2(A1.x, W[d2][1].x, X10); X10 = fma2(A1.y, W[d2][1].y, X10);
                    Y10 = fma2(A0.y, W[d2][0].x, Y10); Y10 = fma2(A0.x, m0, Y10);
                    Y10 = fma2(A1.y, W[d2][1].x, Y10); Y10 = fma2(A1.x, m1, Y10);
                    X11 = fma2(A1.x, W[d2][0].x, X11); X11 = fma2(A1.y, W[d2][0].y, X11);
                    X11 = fma2(A2.x, W[d2][1].x, X11); X11 = fma2(A2.y, W[d2][1].y, X11);
                    Y11 = fma2(A1.y, W[d2][0].x, Y11); Y11 = fma2(A1.x, m0, Y11);
                    Y11 = fma2(A2.y, W[d2][1].x, Y11); Y11 = fma2(A2.x, m1, Y11);
                }
            }
        }
        int u0 = 2 * up, v0 = 2 * vp;
        s_f[img][(u0 * 6 + v0) * 8 + o]           = final_dir(X00, Y00);
        s_f[img][(u0 * 6 + v0 + 1) * 8 + o]       = final_dir(X01, Y01);
        s_f[img][((u0 + 1) * 6 + v0) * 8 + o]     = final_dir(X10, Y10);
        s_f[img][((u0 + 1) * 6 + v0 + 1) * 8 + o] = final_dir(X11, Y11);
    }
    __syncthreads();

    // ---- Phase 4: ring FF. 8-lane group per (img, n); weights from L1 ----
    int g = tid >> 3, l = tid & 7;       // 20 groups = 2 img x 10 outputs
    int img = g / 10, n = g % 10;
    const float4* f4v = (const float4*)s_f[img];
    const float4* fw4 = (const float4*)g_ffwc + n * 144;
    float Sx = 0.f, Sy = 0.f;
    #pragma unroll
    for (int pi = l; pi < 144; pi += 8) {
        float4 f = f4v[pi];
        float4 w = __ldg(fw4 + pi);
        Sx += f.x * w.x + f.y * w.y + f.z * w.z + f.w * w.w;
        Sy += f.y * w.x - f.x * w.y + f.w * w.z - f.z * w.w;
    }
    #pragma unroll
    for (int off = 4; off; off >>= 1) {
        Sx += __shfl_xor_sync(0xffffffff, Sx, off, 8);
        Sy += __shfl_xor_sync(0xffffffff, Sy, off, 8);
    }
    if (l == 0) {
        float inv = rsqrtf(fmaxf(Sx * Sx + Sy * Sy, 1e-36f));
        out[(b * 2 + img) * 10 + n] = Sy * inv;     // sin(atan2(Sy,Sx))
    }
}

extern "C" void kernel_launch(void* const* d_in, const int* in_sizes, int n_in,
                              void* d_out, int out_size) {
    const float* x   = (const float*)d_in[0];   // [B,1,28,28]
    const float* w1  = (const float*)d_in[1];   // [4,1,2,2]
    const float* w2  = (const float*)d_in[2];   // [8,4,4,4]
    const float* ffw = (const float*)d_in[3];   // [288,10]
    float* out = (float*)d_out;                 // [B,10]
    int Bn = in_sizes[0] / 784;

    precompute_weights<<<27, 128>>>(w1, w2, ffw);
    ringnn_kernel<<<Bn / 2, 160>>>(x, out);
}

// round 13
// speedup vs baseline: 1.1479x; 1.1479x over previous
#include <cuda_runtime.h>

typedef unsigned long long ull;

// conv1 weights: plain (cos,sin) per tap, [o][k] k=di*2+dj -> float4 = 2 taps
__device__ __align__(16) float2 g_w1c[16];
// conv2 weights, tap-paired: ulonglong2 per (c,di,djpair,o): .x=(c0,c1) .y=(s0,s1)
//   index = ((c*4+di)*2 + h)*8 + o   (h = dj>>1)
__device__ __align__(16) float g_w2p[2048];
__device__ __align__(16) float2 g_ffwc[2880];  // [n][j] (cos,sin)

__global__ void precompute_weights(const float* __restrict__ w1,
                                   const float* __restrict__ w2,
                                   const float* __restrict__ ffw) {
    int i = blockIdx.x * blockDim.x + threadIdx.x;
    if (i < 16) {
        float s, c; sincosf(w1[i], &s, &c);
        g_w1c[i] = make_float2(c, s);
    } else if (i < 528) {
        int t = i - 16;
        int o = t >> 6, r = t & 63;                  // [o][c][di][dj]
        int cc = r >> 4, di = (r >> 2) & 3, dj = r & 3;
        float s, c; sincosf(w2[t], &s, &c);
        int base = ((((cc * 4 + di) * 2 + (dj >> 1)) * 8 + o)) * 4;
        g_w2p[base + (dj & 1)]     = c;
        g_w2p[base + 2 + (dj & 1)] = s;
    } else if (i < 3408) {
        int t = i - 528;
        int j = t / 10, n = t % 10;                  // [j][n] -> [n][j]
        float s, c; sincosf(ffw[t], &s, &c);
        g_ffwc[n * 288 + j] = make_float2(c, s);
    }
}

// ---- packed f32x2 helpers ----
__device__ __forceinline__ ull pack2(float lo, float hi) {
    ull r; asm("mov.b64 %0, {%1,%2};" : "=l"(r) : "f"(lo), "f"(hi)); return r;
}
__device__ __forceinline__ void unpack2(ull a, float& lo, float& hi) {
    asm("mov.b64 {%0,%1}, %2;" : "=f"(lo), "=f"(hi) : "l"(a));
}
__device__ __forceinline__ ull fma2(ull a, ull b, ull c) {
    ull d; asm("fma.rn.f32x2 %0, %1, %2, %3;" : "=l"(d) : "l"(a), "l"(b), "l"(c));
    return d;
}
// finalize: Sx = X.lo+X.hi ; Sy = (C.lo+C.hi) - (D.lo+D.hi); normalize
__device__ __forceinline__ float2 final_dir3(ull X, ull C, ull D) {
    float xl, xh, cl, ch, dl, dh;
    unpack2(X, xl, xh); unpack2(C, cl, ch); unpack2(D, dl, dh);
    float Sx = xl + xh, Sy = (cl + ch) - (dl + dh);
    float inv = rsqrtf(fmaxf(Sx * Sx + Sy * Sy, 1e-36f));
    return make_float2(Sx * inv, Sy * inv);
}

__global__ __launch_bounds__(160, 6)
void ringnn_kernel(const float* __restrict__ x, float* __restrict__ out) {
    // conv1 out, tap-paired: per (img,c,row i,pair k): { (x0,x1), (y0,y1) }
    __shared__ __align__(16) ulonglong2 s_e1u[2 * 392];   // img*392 + (c*14+i)*7+k
    __shared__ __align__(16) float2 s_f[2][288];          // conv2 out, plain
    __shared__ __align__(16) float4 s_w2[256];            // tap-paired conv2 w

    const int tid = threadIdx.x;
    const int b = blockIdx.x;            // images 2b, 2b+1

    for (int i = tid; i < 256; i += 160)
        s_w2[i] = ((const float4*)g_w2p)[i];  // phase 3 reads after the sync below

    // ---- Phase 1+2 fused: thread = pair of adjacent conv1 patches ----
    const float* xb = x + (size_t)b * 1568;
    for (int t = tid; t < 196; t += 160) {
        int img = t / 98, pp = t % 98;
        int i = pp / 7, k = pp % 7;                 // row i, pair k (cols 4k..4k+3)
        const float* px = xb + img * 784 + (2 * i) * 28 + 4 * k;
        float4 r0 = __ldg((const float4*)px);        // top row, both patches
        float4 r1 = __ldg((const float4*)(px + 28)); // bottom row
        float pc[8], ps[8];                          // patch0: 0..3 ; patch1: 4..7
        __sincosf(r0.x, &ps[0], &pc[0]);
        __sincosf(r0.y, &ps[1], &pc[1]);
        __sincosf(r1.x, &ps[2], &pc[2]);
        __sincosf(r1.y, &ps[3], &pc[3]);
        __sincosf(r0.z, &ps[4], &pc[4]);
        __sincosf(r0.w, &ps[5], &pc[5]);
        __sincosf(r1.z, &ps[6], &pc[6]);
        __sincosf(r1.w, &ps[7], &pc[7]);
        #pragma unroll
        for (int c = 0; c < 4; c++) {
            float4 wa = __ldg((const float4*)g_w1c + c * 2);     // taps 0,1 (c,s,c,s)
            float4 wb = __ldg((const float4*)g_w1c + c * 2 + 1); // taps 2,3
            float S0x, S0y, S1x, S1y;
            S0x = pc[0]*wa.x + ps[0]*wa.y + pc[1]*wa.z + ps[1]*wa.w
                + pc[2]*wb.x + ps[2]*wb.y + pc[3]*wb.z + ps[3]*wb.w;
            S0y = ps[0]*wa.x - pc[0]*wa.y + ps[1]*wa.z - pc[1]*wa.w
                + ps[2]*wb.x - pc[2]*wb.y + ps[3]*wb.z - pc[3]*wb.w;
            S1x = pc[4]*wa.x + ps[4]*wa.y + pc[5]*wa.z + ps[5]*wa.w
                + pc[6]*wb.x + ps[6]*wb.y + pc[7]*wb.z + ps[7]*wb.w;
            S1y = ps[4]*wa.x - pc[4]*wa.y + ps[5]*wa.z - pc[5]*wa.w
                + ps[6]*wb.x - pc[6]*wb.y + ps[7]*wb.z - pc[7]*wb.w;
            float i0 = rsqrtf(fmaxf(S0x*S0x + S0y*S0y, 1e-36f));
            float i1 = rsqrtf(fmaxf(S1x*S1x + S1y*S1y, 1e-36f));
            ulonglong2 e;
            e.x = pack2(S0x * i0, S1x * i1);   // (x0, x1)
            e.y = pack2(S0y * i0, S1y * i1);   // (y0, y1)
            s_e1u[img * 392 + (c * 14 + i) * 7 + k] = e;
        }
    }
    __syncthreads();

    // ---- Phase 3: conv2, 2x2 output tile; X/C/D accumulators (12 chains),
    //      per-c row walk loads each of the 6 needed input rows exactly once.
    if (tid < 144) {
        int img = tid / 72, r = tid % 72;
        int o = r & 7, t9 = r >> 3;
        int up = t9 / 3, vp = t9 % 3;
        const ulonglong2* e1u = s_e1u + img * 392;
        const ulonglong2* w2u = (const ulonglong2*)s_w2;
        ull X00=0, C00=0, D00=0, X01=0, C01=0, D01=0;
        ull X10=0, C10=0, D10=0, X11=0, C11=0, D11=0;
        #pragma unroll
        for (int c = 0; c < 4; c++) {
            ulonglong2 W[4][2];                  // all 8 weight pairs for this c
            #pragma unroll
            for (int di = 0; di < 4; di++) {
                int wb = ((c * 4 + di) * 2) * 8 + o;
                W[di][0] = w2u[wb];              // taps dj0,1: .x=(c0,c1) .y=(s0,s1)
                W[di][1] = w2u[wb + 8];          // taps dj2,3
            }
            int rb = (c * 14 + 4 * up) * 7 + 2 * vp;
            #pragma unroll
            for (int r6 = 0; r6 < 6; r6++) {     // compile-time unrolled; ifs fold
                ulonglong2 A0 = e1u[rb + r6 * 7];
                ulonglong2 A1 = e1u[rb + r6 * 7 + 1];
                ulonglong2 A2 = e1u[rb + r6 * 7 + 2];
                if (r6 < 4) {                    // u0 = 2up, di = r6
                    const ulonglong2 w0 = W[r6][0], w1v = W[r6][1];
                    X00 = fma2(A0.x, w0.x, X00); X00 = fma2(A0.y, w0.y, X00);
                    X00 = fma2(A1.x, w1v.x, X00); X00 = fma2(A1.y, w1v.y, X00);
                    C00 = fma2(A0.y, w0.x, C00); C00 = fma2(A1.y, w1v.x, C00);
                    D00 = fma2(A0.x, w0.y, D00); D00 = fma2(A1.x, w1v.y, D00);
                    X01 = fma2(A1.x, w0.x, X01); X01 = fma2(A1.y, w0.y, X01);
                    X01 = fma2(A2.x, w1v.x, X01); X01 = fma2(A2.y, w1v.y, X01);
                    C01 = fma2(A1.y, w0.x, C01); C01 = fma2(A2.y, w1v.x, C01);
                    D01 = fma2(A1.x, w0.y, D01); D01 = fma2(A2.x, w1v.y, D01);
                }
                if (r6 >= 2) {                   // u1 = 2up+1, di = r6-2
                    const ulonglong2 w0 = W[r6 - 2][0], w1v = W[r6 - 2][1];
                    X10 = fma2(A0.x, w0.x, X10); X10 = fma2(A0.y, w0.y, X10);
                    X10 = fma2(A1.x, w1v.x, X10); X10 = fma2(A1.y, w1v.y, X10);
                    C10 = fma2(A0.y, w0.x, C10); C10 = fma2(A1.y, w1v.x, C10);
                    D10 = fma2(A0.x, w0.y, D10); D10 = fma2(A1.x, w1v.y, D10);
                    X11 = fma2(A1.x, w0.x, X11); X11 = fma2(A1.y, w0.y, X11);
                    X11 = fma2(A2.x, w1v.x, X11); X11 = fma2(A2.y, w1v.y, X11);
                    C11 = fma2(A1.y, w0.x, C11); C11 = fma2(A2.y, w1v.x, C11);
                    D11 = fma2(A1.x, w0.y, D11); D11 = fma2(A2.x, w1v.y, D11);
                }
            }
        }
        int u0 = 2 * up, v0 = 2 * vp;
        s_f[img][(u0 * 6 + v0) * 8 + o]           = final_dir3(X00, C00, D00);
        s_f[img][(u0 * 6 + v0 + 1) * 8 + o]       = final_dir3(X01, C01, D01);
        s_f[img][((u0 + 1) * 6 + v0) * 8 + o]     = final_dir3(X10, C10, D10);
        s_f[img][((u0 + 1) * 6 + v0 + 1) * 8 + o] = final_dir3(X11, C11, D11);
    }
    __syncthreads();

    // ---- Phase 4: ring FF. 8-lane group per (img, n); weights from L1 ----
    int g = tid >> 3, l = tid & 7;       // 20 groups = 2 img x 10 outputs
    int img = g / 10, n = g % 10;
    const float4* f4v = (const float4*)s_f[img];
    const float4* fw4 = (const float4*)g_ffwc + n * 144;
    float Sx = 0.f, Sy = 0.f;
    #pragma unroll
    for (int pi = l; pi < 144; pi += 8) {
        float4 f = f4v[pi];
        float4 w = __ldg(fw4 + pi);
        Sx += f.x * w.x + f.y * w.y + f.z * w.z + f.w * w.w;
        Sy += f.y * w.x - f.x * w.y + f.w * w.z - f.z * w.w;
    }
    #pragma unroll
    for (int off = 4; off; off >>= 1) {
        Sx += __shfl_xor_sync(0xffffffff, Sx, off, 8);
        Sy += __shfl_xor_sync(0xffffffff, Sy, off, 8);
    }
    if (l == 0) {
        float inv = rsqrtf(fmaxf(Sx * Sx + Sy * Sy, 1e-36f));
        out[(b * 2 + img) * 10 + n] = Sy * inv;     // sin(atan2(Sy,Sx))
    }
}

extern "C" void kernel_launch(void* const* d_in, const int* in_sizes, int n_in,
                              void* d_out, int out_size) {
    const float* x   = (const float*)d_in[0];   // [B,1,28,28]
    const float* w1  = (const float*)d_in[1];   // [4,1,2,2]
    const float* w2  = (const float*)d_in[2];   // [8,4,4,4]
    const float* ffw = (const float*)d_in[3];   // [288,10]
    float* out = (float*)d_out;                 // [B,10]
    int Bn = in_sizes[0] / 784;

    precompute_weights<<<27, 128>>>(w1, w2, ffw);
    ringnn_kernel<<<Bn / 2, 160>>>(x, out);
}